// round 3
// baseline (speedup 1.0000x reference)
#include <cuda_runtime.h>

// ---------------------------------------------------------------------------
// GCN_84559316124289 — algebraically collapsed.
//
// Reference broadcasts x to all 27 nodes and returns only node 0's logit.
// With a fixed edge list and identical initial node features:
//   h1[n] = indeg(n) * P1,             P1 = pool(lrelu(conv1(x)+b1))
//   node 0 <- node 1 <- {0,2,4,6}; indeg: d0=1,d2=3,d4=3,d6=5 (sum 12), |in(1)|=4
//   h2[1]  = pool(lrelu(12*conv2w(P1) + 4*b2))
//   h3[0]  = pool(lrelu(conv3(h2[1]) + b3))
//   out[b] = wc . mean_{8x8}(h3[0]) + bc
// => three batch-32 convolutions instead of the full 27-node graph.
// ---------------------------------------------------------------------------

#define LRELU(t) ((t) > 0.f ? (t) : 0.2f * (t))

// Scratch (no runtime allocation allowed)
__device__ float g_P1[32 * 32 * 32 * 32];   // [B=32, 32, 32, 32]  4 MB
__device__ float g_H2[32 * 64 * 16 * 16];   // [B=32, 64, 16, 16]  2 MB

// ---------------------------------------------------------------------------
// Kernel 1: conv1 (4->32, 3x3 SAME) + lrelu + maxpool2  on x[32,4,64,64]
// grid (32 batches, 8 cout-groups of 4), block 256, each thread 4 pooled px.
// ---------------------------------------------------------------------------
__global__ void k1_conv(const float* __restrict__ x,
                        const float* __restrict__ w1,
                        const float* __restrict__ b1) {
    extern __shared__ float sm[];
    float* s_in = sm;                 // 4*66*66 = 17424 floats (zero-padded)
    float* s_w  = sm + 4 * 66 * 66;   // 4co*4ci*9 = 144 floats

    const int b  = blockIdx.x;
    const int cg = blockIdx.y;        // couts [cg*4, cg*4+4)
    const int tid = threadIdx.x;

    const float* xb = x + b * (4 * 64 * 64);
    for (int i = tid; i < 4 * 66 * 66; i += 256) {
        int c = i / 4356;  int r = i - c * 4356;
        int iy = r / 66;   int ix = r - iy * 66;
        int gy = iy - 1, gx = ix - 1;
        float v = 0.f;
        if ((unsigned)gy < 64u && (unsigned)gx < 64u) v = xb[c * 4096 + gy * 64 + gx];
        s_in[i] = v;
    }
    for (int i = tid; i < 144; i += 256) s_w[i] = w1[cg * 144 + i];
    __syncthreads();

    for (int p = 0; p < 4; p++) {
        int pi = p * 256 + tid;
        int ph = pi >> 5, pw = pi & 31;
        float acc[4][4];
        #pragma unroll
        for (int co = 0; co < 4; co++)
            #pragma unroll
            for (int q = 0; q < 4; q++) acc[co][q] = 0.f;

        #pragma unroll
        for (int ci = 0; ci < 4; ci++) {
            float patch[4][4];
            #pragma unroll
            for (int r = 0; r < 4; r++)
                #pragma unroll
                for (int c2 = 0; c2 < 4; c2++)
                    patch[r][c2] = s_in[ci * 4356 + (2 * ph + r) * 66 + (2 * pw + c2)];
            #pragma unroll
            for (int co = 0; co < 4; co++) {
                float w[9];
                #pragma unroll
                for (int k = 0; k < 9; k++) w[k] = s_w[(co * 4 + ci) * 9 + k];
                #pragma unroll
                for (int dy = 0; dy < 2; dy++)
                    #pragma unroll
                    for (int dx = 0; dx < 2; dx++) {
                        float s = acc[co][dy * 2 + dx];
                        #pragma unroll
                        for (int ky = 0; ky < 3; ky++)
                            #pragma unroll
                            for (int kx = 0; kx < 3; kx++)
                                s += patch[dy + ky][dx + kx] * w[ky * 3 + kx];
                        acc[co][dy * 2 + dx] = s;
                    }
            }
        }
        #pragma unroll
        for (int co = 0; co < 4; co++) {
            float bb = b1[cg * 4 + co];
            float m = -1e30f;
            #pragma unroll
            for (int q = 0; q < 4; q++) {
                float t = acc[co][q] + bb;
                t = LRELU(t);
                m = fmaxf(m, t);
            }
            g_P1[((b * 32) + (cg * 4 + co)) * 1024 + ph * 32 + pw] = m;
        }
    }
}

// ---------------------------------------------------------------------------
// Kernel 2: 12*conv2w (32->64) + 4*b2, lrelu, maxpool2  on P1[32,32,32,32]
// grid (32, 4 cout-groups of 16), block 512 (256 pooled px x 2 cout halves).
// ---------------------------------------------------------------------------
__global__ void k2_conv(const float* __restrict__ w2,
                        const float* __restrict__ b2) {
    extern __shared__ float sm[];
    float* s_in = sm;                 // 32*34*34 = 36992 floats
    float* s_w  = sm + 36992;         // 16co*32ci*9 = 4608 floats

    const int b  = blockIdx.x;
    const int cg = blockIdx.y;        // couts [cg*16, cg*16+16)
    const int tid = threadIdx.x;

    const float* pb = g_P1 + b * (32 * 32 * 32);
    for (int i = tid; i < 36992; i += 512) {
        int c = i / 1156;  int r = i - c * 1156;
        int iy = r / 34;   int ix = r - iy * 34;
        int gy = iy - 1, gx = ix - 1;
        float v = 0.f;
        if ((unsigned)gy < 32u && (unsigned)gx < 32u) v = pb[c * 1024 + gy * 32 + gx];
        s_in[i] = v;
    }
    for (int i = tid; i < 16 * 32 * 9; i += 512) s_w[i] = w2[cg * (16 * 288) + i];
    __syncthreads();

    const int pix = tid & 255;
    const int sub = tid >> 8;         // 0..1 -> 8 couts each
    const int ph = pix >> 4, pw = pix & 15;

    float acc[8][4];
    #pragma unroll
    for (int j = 0; j < 8; j++)
        #pragma unroll
        for (int q = 0; q < 4; q++) acc[j][q] = 0.f;

    for (int ci = 0; ci < 32; ci++) {
        float patch[4][4];
        #pragma unroll
        for (int r = 0; r < 4; r++)
            #pragma unroll
            for (int c2 = 0; c2 < 4; c2++)
                patch[r][c2] = s_in[ci * 1156 + (2 * ph + r) * 34 + (2 * pw + c2)];
        #pragma unroll
        for (int j = 0; j < 8; j++) {
            int co = sub * 8 + j;
            float w[9];
            #pragma unroll
            for (int k = 0; k < 9; k++) w[k] = s_w[(co * 32 + ci) * 9 + k];
            #pragma unroll
            for (int dy = 0; dy < 2; dy++)
                #pragma unroll
                for (int dx = 0; dx < 2; dx++) {
                    float s = acc[j][dy * 2 + dx];
                    #pragma unroll
                    for (int ky = 0; ky < 3; ky++)
                        #pragma unroll
                        for (int kx = 0; kx < 3; kx++)
                            s += patch[dy + ky][dx + kx] * w[ky * 3 + kx];
                    acc[j][dy * 2 + dx] = s;
                }
        }
    }
    #pragma unroll
    for (int j = 0; j < 8; j++) {
        int cog = cg * 16 + sub * 8 + j;
        float bb = 4.f * b2[cog];
        float m = -1e30f;
        #pragma unroll
        for (int q = 0; q < 4; q++) {
            float t = 12.f * acc[j][q] + bb;
            t = LRELU(t);
            m = fmaxf(m, t);
        }
        g_H2[(b * 64 + cog) * 256 + ph * 16 + pw] = m;
    }
}

// ---------------------------------------------------------------------------
// Kernel 3: conv3 (64->128) + b3, lrelu, maxpool2, spatial mean, dot with wc.
// grid (32, 4 cout-groups of 32), block 512 (64 pooled px x 8 cout subgroups).
// Partial logits accumulated with atomicAdd into out[b] (init kernel wrote bc).
// ---------------------------------------------------------------------------
__global__ void k3_conv(const float* __restrict__ w3,
                        const float* __restrict__ b3,
                        const float* __restrict__ wc,
                        float* __restrict__ out) {
    extern __shared__ float sm[];
    float* s_in  = sm;                   // 64*18*18 = 20736 floats
    float* s_w   = sm + 20736;           // 32co*64ci*9 = 18432 floats
    float* s_red = s_w + 18432;          // 32*64 = 2048 floats

    const int b  = blockIdx.x;
    const int cg = blockIdx.y;           // couts [cg*32, cg*32+32)
    const int tid = threadIdx.x;

    const float* hb = g_H2 + b * (64 * 16 * 16);
    for (int i = tid; i < 20736; i += 512) {
        int c = i / 324;  int r = i - c * 324;
        int iy = r / 18;  int ix = r - iy * 18;
        int gy = iy - 1, gx = ix - 1;
        float v = 0.f;
        if ((unsigned)gy < 16u && (unsigned)gx < 16u) v = hb[c * 256 + gy * 16 + gx];
        s_in[i] = v;
    }
    for (int i = tid; i < 18432; i += 512) s_w[i] = w3[cg * (32 * 576) + i];
    __syncthreads();

    const int pix = tid & 63;
    const int sub = tid >> 6;            // 0..7 -> 4 couts each
    const int ph = pix >> 3, pw = pix & 7;

    float acc[4][4];
    #pragma unroll
    for (int j = 0; j < 4; j++)
        #pragma unroll
        for (int q = 0; q < 4; q++) acc[j][q] = 0.f;

    for (int ci = 0; ci < 64; ci++) {
        float patch[4][4];
        #pragma unroll
        for (int r = 0; r < 4; r++)
            #pragma unroll
            for (int c2 = 0; c2 < 4; c2++)
                patch[r][c2] = s_in[ci * 324 + (2 * ph + r) * 18 + (2 * pw + c2)];
        #pragma unroll
        for (int j = 0; j < 4; j++) {
            int co = sub * 4 + j;
            float w[9];
            #pragma unroll
            for (int k = 0; k < 9; k++) w[k] = s_w[(co * 64 + ci) * 9 + k];
            #pragma unroll
            for (int dy = 0; dy < 2; dy++)
                #pragma unroll
                for (int dx = 0; dx < 2; dx++) {
                    float s = acc[j][dy * 2 + dx];
                    #pragma unroll
                    for (int ky = 0; ky < 3; ky++)
                        #pragma unroll
                        for (int kx = 0; kx < 3; kx++)
                            s += patch[dy + ky][dx + kx] * w[ky * 3 + kx];
                    acc[j][dy * 2 + dx] = s;
                }
        }
    }
    #pragma unroll
    for (int j = 0; j < 4; j++) {
        int co = sub * 4 + j;
        float bb = b3[cg * 32 + co];
        float m = -1e30f;
        #pragma unroll
        for (int q = 0; q < 4; q++) {
            float t = acc[j][q] + bb;
            t = LRELU(t);
            m = fmaxf(m, t);
        }
        s_red[co * 64 + pix] = m;
    }
    __syncthreads();

    if (tid < 32) {
        float s = 0.f;
        #pragma unroll 8
        for (int p2 = 0; p2 < 64; p2++) s += s_red[tid * 64 + p2];
        float part = wc[cg * 32 + tid] * s * (1.0f / 64.0f);
        #pragma unroll
        for (int off = 16; off; off >>= 1)
            part += __shfl_down_sync(0xffffffffu, part, off);
        if (tid == 0) atomicAdd(&out[b], part);
    }
}

// out[b] = bc before k3's atomic accumulation.
__global__ void k_init(float* __restrict__ out, const float* __restrict__ bc) {
    if (threadIdx.x < 32) out[threadIdx.x] = bc[0];
}

extern "C" void kernel_launch(void* const* d_in, const int* in_sizes, int n_in,
                              void* d_out, int out_size) {
    const float* x  = (const float*)d_in[0];
    const float* w1 = (const float*)d_in[1];
    const float* b1 = (const float*)d_in[2];
    const float* w2 = (const float*)d_in[3];
    const float* b2 = (const float*)d_in[4];
    const float* w3 = (const float*)d_in[5];
    const float* b3 = (const float*)d_in[6];
    const float* wc = (const float*)d_in[7];
    const float* bc = (const float*)d_in[8];
    float* out = (float*)d_out;

    const size_t sm1 = (4 * 66 * 66 + 144) * sizeof(float);            //  70 KB
    const size_t sm2 = (36992 + 4608) * sizeof(float);                 // 166 KB
    const size_t sm3 = (20736 + 18432 + 2048) * sizeof(float);         // 165 KB

    cudaFuncSetAttribute(k1_conv, cudaFuncAttributeMaxDynamicSharedMemorySize, (int)sm1);
    cudaFuncSetAttribute(k2_conv, cudaFuncAttributeMaxDynamicSharedMemorySize, (int)sm2);
    cudaFuncSetAttribute(k3_conv, cudaFuncAttributeMaxDynamicSharedMemorySize, (int)sm3);

    k1_conv<<<dim3(32, 8), 256, sm1>>>(x, w1, b1);
    k2_conv<<<dim3(32, 4), 512, sm2>>>(w2, b2);
    k_init<<<1, 32>>>(out, bc);
    k3_conv<<<dim3(32, 4), 512, sm3>>>(w3, b3, wc, out);
}

// round 5
// speedup vs baseline: 1.0608x; 1.0608x over previous
#include <cuda_runtime.h>

// ---------------------------------------------------------------------------
// GCN_84559316124289 — algebraically collapsed + packed f32x2 FMA.
//
//   h1[n] = indeg(n) * P1,  P1 = pool(lrelu(conv1(x)+b1))
//   h2[1] = pool(lrelu(12*conv2w(P1) + 4*b2))
//   h3[0] = pool(lrelu(conv3(h2[1]) + b3))
//   out[b] = wc . mean(h3[0]) + bc
//
// Packing: FFMA2 over adjacent cout pairs. Weights staged in smem as
// [ci][k][co] so one LDS.128 yields two (co,co+1) f32x2 operand pairs;
// patch values duplicated once per ci via mov.b64 {x,x}.
// ---------------------------------------------------------------------------

typedef unsigned long long ull;

__device__ __forceinline__ ull dup2(float x) {
    ull r; asm("mov.b64 %0, {%1, %1};" : "=l"(r) : "f"(x)); return r;
}
__device__ __forceinline__ void ffma2(ull& d, ull a, ull b) {
    asm("fma.rn.f32x2 %0, %1, %2, %0;" : "+l"(d) : "l"(a), "l"(b));
}
__device__ __forceinline__ void unpk(float& lo, float& hi, ull v) {
    asm("mov.b64 {%0, %1}, %2;" : "=f"(lo), "=f"(hi) : "l"(v));
}

#define LRELU(t) ((t) > 0.f ? (t) : 0.2f * (t))

// Scratch (no runtime allocation allowed)
__device__ float g_P1[32 * 32 * 32 * 32];   // [B, 32, 32, 32]
__device__ float g_H2[32 * 64 * 16 * 16];   // [B, 64, 16, 16]

// ---------------------------------------------------------------------------
// Kernel 1: conv1 (4->32) + lrelu + maxpool2.  grid(32,8) block 256.
// s_in: 4ch x 66 rows x stride 68.  s_w: [ci][k][co0..3].
// ---------------------------------------------------------------------------
__global__ void __launch_bounds__(256, 1)
k1_conv(const float* __restrict__ x,
        const float* __restrict__ w1,
        const float* __restrict__ b1) {
    extern __shared__ float sm[];
    float* s_in = sm;                  // 4*66*68 = 17952
    float* s_w  = sm + 17952;          // 4ci*9k*4co = 144

    const int b  = blockIdx.x;
    const int cg = blockIdx.y;
    const int tid = threadIdx.x;

    const float* xb = x + b * (4 * 4096);
    for (int i = tid; i < 4 * 66 * 68; i += 256) {
        int c = i / 4488; int r = i - c * 4488;
        int iy = r / 68;  int ix = r - iy * 68;
        int gy = iy - 1, gx = ix - 1;
        float v = 0.f;
        if ((unsigned)gy < 64u && (unsigned)gx < 64u) v = xb[c * 4096 + gy * 64 + gx];
        s_in[i] = v;
    }
    for (int i = tid; i < 144; i += 256) {
        int co = i / 36; int r = i - co * 36;
        int ci = r / 9;  int k = r - ci * 9;
        s_w[(ci * 9 + k) * 4 + co] = w1[cg * 144 + i];
    }
    __syncthreads();

    for (int p = 0; p < 4; p++) {
        int pi = p * 256 + tid;
        int ph = pi >> 5, pw = pi & 31;
        ull acc[2][4];
        #pragma unroll
        for (int j = 0; j < 2; j++)
            #pragma unroll
            for (int q = 0; q < 4; q++) acc[j][q] = 0ull;

        #pragma unroll
        for (int ci = 0; ci < 4; ci++) {
            const float* pb = s_in + ci * 4488 + (2 * ph) * 68 + 2 * pw;
            ull pd[4][4];
            #pragma unroll
            for (int r = 0; r < 4; r++) {
                float2 a = *(const float2*)(pb + r * 68);
                float2 c2 = *(const float2*)(pb + r * 68 + 2);
                pd[r][0] = dup2(a.x); pd[r][1] = dup2(a.y);
                pd[r][2] = dup2(c2.x); pd[r][3] = dup2(c2.y);
            }
            const float* wp = s_w + ci * 36;
            #pragma unroll
            for (int k = 0; k < 9; k++) {
                ulonglong2 w = *(const ulonglong2*)(wp + k * 4);
                int ky = k / 3, kx = k - ky * 3;
                #pragma unroll
                for (int dy = 0; dy < 2; dy++)
                    #pragma unroll
                    for (int dx = 0; dx < 2; dx++) {
                        ffma2(acc[0][dy * 2 + dx], pd[dy + ky][dx + kx], w.x);
                        ffma2(acc[1][dy * 2 + dx], pd[dy + ky][dx + kx], w.y);
                    }
            }
        }
        #pragma unroll
        for (int j = 0; j < 2; j++) {
            float v0[4], v1[4];
            #pragma unroll
            for (int q = 0; q < 4; q++) unpk(v0[q], v1[q], acc[j][q]);
            int co0 = cg * 4 + j * 2;
            float bb0 = b1[co0], bb1 = b1[co0 + 1];
            float m0 = -1e30f, m1 = -1e30f;
            #pragma unroll
            for (int q = 0; q < 4; q++) {
                float t0 = v0[q] + bb0; t0 = LRELU(t0); m0 = fmaxf(m0, t0);
                float t1 = v1[q] + bb1; t1 = LRELU(t1); m1 = fmaxf(m1, t1);
            }
            g_P1[(b * 32 + co0) * 1024 + ph * 32 + pw] = m0;
            g_P1[(b * 32 + co0 + 1) * 1024 + ph * 32 + pw] = m1;
        }
    }
}

// ---------------------------------------------------------------------------
// Kernel 2: 12*conv2w (32->64) + 4*b2, lrelu, pool.  grid(32,4) block 512.
// 256 px x 2 subs of 8 couts (4 pairs). s_in 32ch x 34 x stride 36.
// ---------------------------------------------------------------------------
__global__ void __launch_bounds__(512, 1)
k2_conv(const float* __restrict__ w2,
        const float* __restrict__ b2) {
    extern __shared__ float sm[];
    float* s_in = sm;                  // 32*34*36 = 39168
    float* s_w  = sm + 39168;          // 32ci*9k*16co = 4608

    const int b  = blockIdx.x;
    const int cg = blockIdx.y;
    const int tid = threadIdx.x;

    const float* pb = g_P1 + b * (32 * 1024);
    for (int i = tid; i < 39168; i += 512) {
        int c = i / 1224; int r = i - c * 1224;
        int iy = r / 36;  int ix = r - iy * 36;
        int gy = iy - 1, gx = ix - 1;
        float v = 0.f;
        if ((unsigned)gy < 32u && (unsigned)gx < 32u) v = pb[c * 1024 + gy * 32 + gx];
        s_in[i] = v;
    }
    for (int i = tid; i < 4608; i += 512) {
        int co = i / 288; int r = i - co * 288;
        int ci = r / 9;   int k = r - ci * 9;
        s_w[(ci * 9 + k) * 16 + co] = w2[cg * 4608 + i];
    }
    __syncthreads();

    const int pix = tid & 255;
    const int sub = tid >> 8;          // 0..1, 8 couts each
    const int ph = pix >> 4, pw = pix & 15;

    ull acc[4][4];
    #pragma unroll
    for (int j = 0; j < 4; j++)
        #pragma unroll
        for (int q = 0; q < 4; q++) acc[j][q] = 0ull;

    for (int ci = 0; ci < 32; ci++) {
        const float* ib = s_in + ci * 1224 + (2 * ph) * 36 + 2 * pw;
        ull pd[4][4];
        #pragma unroll
        for (int r = 0; r < 4; r++) {
            float2 a = *(const float2*)(ib + r * 36);
            float2 c2 = *(const float2*)(ib + r * 36 + 2);
            pd[r][0] = dup2(a.x); pd[r][1] = dup2(a.y);
            pd[r][2] = dup2(c2.x); pd[r][3] = dup2(c2.y);
        }
        const float* wp = s_w + ci * 144 + sub * 8;
        #pragma unroll
        for (int k = 0; k < 9; k++) {
            ulonglong2 wA = *(const ulonglong2*)(wp + k * 16);
            ulonglong2 wB = *(const ulonglong2*)(wp + k * 16 + 4);
            int ky = k / 3, kx = k - ky * 3;
            #pragma unroll
            for (int dy = 0; dy < 2; dy++)
                #pragma unroll
                for (int dx = 0; dx < 2; dx++) {
                    ull pv = pd[dy + ky][dx + kx];
                    int q = dy * 2 + dx;
                    ffma2(acc[0][q], pv, wA.x);
                    ffma2(acc[1][q], pv, wA.y);
                    ffma2(acc[2][q], pv, wB.x);
                    ffma2(acc[3][q], pv, wB.y);
                }
        }
    }
    #pragma unroll
    for (int j = 0; j < 4; j++) {
        float v0[4], v1[4];
        #pragma unroll
        for (int q = 0; q < 4; q++) unpk(v0[q], v1[q], acc[j][q]);
        int co0 = cg * 16 + sub * 8 + j * 2;
        float bb0 = 4.f * b2[co0], bb1 = 4.f * b2[co0 + 1];
        float m0 = -1e30f, m1 = -1e30f;
        #pragma unroll
        for (int q = 0; q < 4; q++) {
            float t0 = 12.f * v0[q] + bb0; t0 = LRELU(t0); m0 = fmaxf(m0, t0);
            float t1 = 12.f * v1[q] + bb1; t1 = LRELU(t1); m1 = fmaxf(m1, t1);
        }
        g_H2[(b * 64 + co0) * 256 + ph * 16 + pw] = m0;
        g_H2[(b * 64 + co0 + 1) * 256 + ph * 16 + pw] = m1;
    }
}

// ---------------------------------------------------------------------------
// Kernel 3: conv3 (64->128) + lrelu + pool + mean + dot(wc).  grid(32,4), 512.
// 64 px x 8 subs of 4 couts (2 pairs). s_in 64ch x 18 x stride 20.
// ---------------------------------------------------------------------------
__global__ void __launch_bounds__(512, 1)
k3_conv(const float* __restrict__ w3,
        const float* __restrict__ b3,
        const float* __restrict__ wc,
        float* __restrict__ out) {
    extern __shared__ float sm[];
    float* s_in  = sm;                 // 64*18*20 = 23040
    float* s_w   = sm + 23040;         // 64ci*9k*32co = 18432
    float* s_red = s_w + 18432;        // 32*65 = 2080 (padded: no bank conflicts)

    const int b  = blockIdx.x;
    const int cg = blockIdx.y;
    const int tid = threadIdx.x;

    const float* hb = g_H2 + b * (64 * 256);
    for (int i = tid; i < 23040; i += 512) {
        int c = i / 360; int r = i - c * 360;
        int iy = r / 20; int ix = r - iy * 20;
        int gy = iy - 1, gx = ix - 1;
        float v = 0.f;
        if ((unsigned)gy < 16u && (unsigned)gx < 16u) v = hb[c * 256 + gy * 16 + gx];
        s_in[i] = v;
    }
    for (int i = tid; i < 18432; i += 512) {
        int co = i / 576; int r = i - co * 576;
        int ci = r / 9;   int k = r - ci * 9;
        s_w[(ci * 9 + k) * 32 + co] = w3[cg * 18432 + i];
    }
    __syncthreads();

    const int pix = tid & 63;
    const int sub = tid >> 6;          // 0..7, 4 couts each
    const int ph = pix >> 3, pw = pix & 7;

    ull acc[2][4];
    #pragma unroll
    for (int j = 0; j < 2; j++)
        #pragma unroll
        for (int q = 0; q < 4; q++) acc[j][q] = 0ull;

    for (int ci = 0; ci < 64; ci++) {
        const float* ib = s_in + ci * 360 + (2 * ph) * 20 + 2 * pw;
        ull pd[4][4];
        #pragma unroll
        for (int r = 0; r < 4; r++) {
            float2 a = *(const float2*)(ib + r * 20);
            float2 c2 = *(const float2*)(ib + r * 20 + 2);
            pd[r][0] = dup2(a.x); pd[r][1] = dup2(a.y);
            pd[r][2] = dup2(c2.x); pd[r][3] = dup2(c2.y);
        }
        const float* wp = s_w + ci * 288 + sub * 4;
        #pragma unroll
        for (int k = 0; k < 9; k++) {
            ulonglong2 w = *(const ulonglong2*)(wp + k * 32);
            int ky = k / 3, kx = k - ky * 3;
            #pragma unroll
            for (int dy = 0; dy < 2; dy++)
                #pragma unroll
                for (int dx = 0; dx < 2; dx++) {
                    ull pv = pd[dy + ky][dx + kx];
                    int q = dy * 2 + dx;
                    ffma2(acc[0][q], pv, w.x);
                    ffma2(acc[1][q], pv, w.y);
                }
        }
    }
    #pragma unroll
    for (int j = 0; j < 2; j++) {
        float v0[4], v1[4];
        #pragma unroll
        for (int q = 0; q < 4; q++) unpk(v0[q], v1[q], acc[j][q]);
        int co0 = sub * 4 + j * 2;
        float bb0 = b3[cg * 32 + co0], bb1 = b3[cg * 32 + co0 + 1];
        float m0 = -1e30f, m1 = -1e30f;
        #pragma unroll
        for (int q = 0; q < 4; q++) {
            float t0 = v0[q] + bb0; t0 = LRELU(t0); m0 = fmaxf(m0, t0);
            float t1 = v1[q] + bb1; t1 = LRELU(t1); m1 = fmaxf(m1, t1);
        }
        s_red[co0 * 65 + pix] = m0;
        s_red[(co0 + 1) * 65 + pix] = m1;
    }
    __syncthreads();

    if (tid < 32) {
        float s = 0.f;
        #pragma unroll 8
        for (int p2 = 0; p2 < 64; p2++) s += s_red[tid * 65 + p2];
        float part = wc[cg * 32 + tid] * s * (1.0f / 64.0f);
        #pragma unroll
        for (int off = 16; off; off >>= 1)
            part += __shfl_down_sync(0xffffffffu, part, off);
        if (tid == 0) atomicAdd(&out[b], part);
    }
}

// out[b] = bc before k3's atomic accumulation.
__global__ void k_init(float* __restrict__ out, const float* __restrict__ bc) {
    if (threadIdx.x < 32) out[threadIdx.x] = bc[0];
}

extern "C" void kernel_launch(void* const* d_in, const int* in_sizes, int n_in,
                              void* d_out, int out_size) {
    const float* x  = (const float*)d_in[0];
    const float* w1 = (const float*)d_in[1];
    const float* b1 = (const float*)d_in[2];
    const float* w2 = (const float*)d_in[3];
    const float* b2 = (const float*)d_in[4];
    const float* w3 = (const float*)d_in[5];
    const float* b3 = (const float*)d_in[6];
    const float* wc = (const float*)d_in[7];
    const float* bc = (const float*)d_in[8];
    float* out = (float*)d_out;

    const size_t sm1 = (17952 + 144) * sizeof(float);          //  72 KB
    const size_t sm2 = (39168 + 4608) * sizeof(float);         // 175 KB
    const size_t sm3 = (23040 + 18432 + 2080) * sizeof(float); // 174 KB

    cudaFuncSetAttribute(k1_conv, cudaFuncAttributeMaxDynamicSharedMemorySize, (int)sm1);
    cudaFuncSetAttribute(k2_conv, cudaFuncAttributeMaxDynamicSharedMemorySize, (int)sm2);
    cudaFuncSetAttribute(k3_conv, cudaFuncAttributeMaxDynamicSharedMemorySize, (int)sm3);

    k1_conv<<<dim3(32, 8), 256, sm1>>>(x, w1, b1);
    k2_conv<<<dim3(32, 4), 512, sm2>>>(w2, b2);
    k_init<<<1, 32>>>(out, bc);
    k3_conv<<<dim3(32, 4), 512, sm3>>>(w3, b3, wc, out);
}

// round 6
// speedup vs baseline: 1.1623x; 1.0956x over previous
#include <cuda_runtime.h>

// ---------------------------------------------------------------------------
// GCN_84559316124289 — algebraically collapsed + f32x2 FMA + 2x2-pooled-block
// register tiling (raises FMA-per-L1-wavefront ~3x; prior kernel was
// L1-wavefront bound at 61.7%).
//
//   P1 = pool(lrelu(conv1(x)+b1))
//   H2 = pool(lrelu(12*conv2w(P1) + 4*b2))
//   H3 = pool(lrelu(conv3(H2)+b3));  out[b] = wc . mean(H3) + bc
//
// Each thread: 4 couts (2 f32x2 pairs) x 16 conv px (4x4 -> 2x2 pooled).
// Patch 6x6 dup'd to f32x2 once per ci; weights [ci][k][co] so one LDS.128
// yields both cout-pairs.
// ---------------------------------------------------------------------------

typedef unsigned long long ull;

__device__ __forceinline__ ull dup2(float x) {
    ull r; asm("mov.b64 %0, {%1, %1};" : "=l"(r) : "f"(x)); return r;
}
__device__ __forceinline__ void ffma2(ull& d, ull a, ull b) {
    asm("fma.rn.f32x2 %0, %1, %2, %0;" : "+l"(d) : "l"(a), "l"(b));
}
__device__ __forceinline__ void unpk(float& lo, float& hi, ull v) {
    asm("mov.b64 {%0, %1}, %2;" : "=f"(lo), "=f"(hi) : "l"(v));
}

#define LRELU(t) ((t) > 0.f ? (t) : 0.2f * (t))

__device__ float g_P1[32 * 32 * 32 * 32];   // [B, 32, 32, 32]
__device__ float g_H2[32 * 64 * 16 * 16];   // [B, 64, 16, 16]

// Shared conv micro-kernel: 6x6 patch (dup'd), 9 weight LDS.128, 32 FFMA2/k.
// RS = s_in row stride (floats), NCO = couts staged per block.
#define CONV_CI_BODY(IB, WP, RS, NCO)                                          \
    {                                                                          \
        ull pd[6][6];                                                          \
        _Pragma("unroll")                                                      \
        for (int r = 0; r < 6; r++) {                                          \
            float4 a4 = *(const float4*)((IB) + r * (RS));                     \
            float2 b2v = *(const float2*)((IB) + r * (RS) + 4);                \
            pd[r][0] = dup2(a4.x); pd[r][1] = dup2(a4.y);                      \
            pd[r][2] = dup2(a4.z); pd[r][3] = dup2(a4.w);                      \
            pd[r][4] = dup2(b2v.x); pd[r][5] = dup2(b2v.y);                    \
        }                                                                      \
        _Pragma("unroll")                                                      \
        for (int k = 0; k < 9; k++) {                                          \
            ulonglong2 w = *(const ulonglong2*)((WP) + k * (NCO));             \
            int ky = k / 3, kx = k - ky * 3;                                   \
            _Pragma("unroll")                                                  \
            for (int dy = 0; dy < 4; dy++)                                     \
                _Pragma("unroll")                                              \
                for (int dx = 0; dx < 4; dx++) {                               \
                    ull pv = pd[dy + ky][dx + kx];                             \
                    ffma2(acc[0][dy * 4 + dx], pv, w.x);                       \
                    ffma2(acc[1][dy * 4 + dx], pv, w.y);                       \
                }                                                              \
        }                                                                      \
    }

// ---------------------------------------------------------------------------
// Kernel 1: conv1 (4->32) + lrelu + pool.  grid(32,8) block 256.
// 256 threads = 16x16 pooled-blocks, all on the same 4 couts.
// s_in: 4ch x 66 x stride 68.  s_w: [ci][k][co0..3].
// ---------------------------------------------------------------------------
__global__ void __launch_bounds__(256, 1)
k1_conv(const float* __restrict__ x,
        const float* __restrict__ w1,
        const float* __restrict__ b1) {
    extern __shared__ float sm[];
    float* s_in = sm;                  // 4*66*68 = 17952
    float* s_w  = sm + 17952;          // 144

    const int b  = blockIdx.x;
    const int cg = blockIdx.y;
    const int tid = threadIdx.x;

    for (int i = tid * 4; i < 17952; i += 1024)
        *(float4*)(s_in + i) = make_float4(0.f, 0.f, 0.f, 0.f);
    if (tid < 144) {
        int co = tid / 36; int r = tid - co * 36;
        int ci = r / 9;    int k = r - ci * 9;
        s_w[(ci * 9 + k) * 4 + co] = w1[cg * 144 + tid];
    }
    __syncthreads();

    const float* xb = x + b * (4 * 4096);
    for (int i = tid; i < 4 * 64 * 64; i += 256) {
        int c = i >> 12, r = (i >> 6) & 63, xx = i & 63;
        s_in[c * 4488 + (r + 1) * 68 + (xx + 1)] = xb[i];
    }
    __syncthreads();

    const int pbh = tid >> 4, pbw = tid & 15;

    ull acc[2][16];
    #pragma unroll
    for (int j = 0; j < 2; j++)
        #pragma unroll
        for (int q = 0; q < 16; q++) acc[j][q] = 0ull;

    #pragma unroll
    for (int ci = 0; ci < 4; ci++) {
        const float* ib = s_in + ci * 4488 + (4 * pbh) * 68 + 4 * pbw;
        const float* wp = s_w + ci * 36;
        CONV_CI_BODY(ib, wp, 68, 4)
    }

    #pragma unroll
    for (int j = 0; j < 2; j++) {
        float v0[16], v1[16];
        #pragma unroll
        for (int q = 0; q < 16; q++) unpk(v0[q], v1[q], acc[j][q]);
        int co0 = cg * 4 + j * 2;
        float bb0 = b1[co0], bb1 = b1[co0 + 1];
        #pragma unroll
        for (int i = 0; i < 2; i++)
            #pragma unroll
            for (int jj = 0; jj < 2; jj++) {
                float m0 = -1e30f, m1 = -1e30f;
                #pragma unroll
                for (int dy = 0; dy < 2; dy++)
                    #pragma unroll
                    for (int dx = 0; dx < 2; dx++) {
                        int q = (2 * i + dy) * 4 + (2 * jj + dx);
                        float t0 = v0[q] + bb0; t0 = LRELU(t0); m0 = fmaxf(m0, t0);
                        float t1 = v1[q] + bb1; t1 = LRELU(t1); m1 = fmaxf(m1, t1);
                    }
                int py = 2 * pbh + i, px = 2 * pbw + jj;
                g_P1[(b * 32 + co0) * 1024 + py * 32 + px] = m0;
                g_P1[(b * 32 + co0 + 1) * 1024 + py * 32 + px] = m1;
            }
    }
}

// ---------------------------------------------------------------------------
// Kernel 2: 12*conv2w (32->64) + 4*b2, lrelu, pool.  grid(32,4) block 256.
// 256 threads = 64 pooled-blocks (8x8) x 4 cout-subgroups (4 couts each).
// s_in: 32ch x 34 x stride 36.  s_w: [ci][k][co0..15].
// ---------------------------------------------------------------------------
__global__ void __launch_bounds__(256, 1)
k2_conv(const float* __restrict__ w2,
        const float* __restrict__ b2) {
    extern __shared__ float sm[];
    float* s_in = sm;                  // 32*34*36 = 39168
    float* s_w  = sm + 39168;          // 4608

    const int b  = blockIdx.x;
    const int cg = blockIdx.y;
    const int tid = threadIdx.x;

    for (int i = tid * 4; i < 39168; i += 1024)
        *(float4*)(s_in + i) = make_float4(0.f, 0.f, 0.f, 0.f);
    for (int i = tid; i < 4608; i += 256) {
        int co = i / 288; int r = i - co * 288;
        int ci = r / 9;   int k = r - ci * 9;
        s_w[(ci * 9 + k) * 16 + co] = w2[cg * 4608 + i];
    }
    __syncthreads();

    const float* pb = g_P1 + b * (32 * 1024);
    for (int i = tid; i < 32 * 32 * 32; i += 256) {
        int c = i >> 10, r = (i >> 5) & 31, xx = i & 31;
        s_in[c * 1224 + (r + 1) * 36 + (xx + 1)] = pb[i];
    }
    __syncthreads();

    const int px = tid & 63;
    const int sub = tid >> 6;          // 0..3 -> 4 couts each
    const int pbh = px >> 3, pbw = px & 7;

    ull acc[2][16];
    #pragma unroll
    for (int j = 0; j < 2; j++)
        #pragma unroll
        for (int q = 0; q < 16; q++) acc[j][q] = 0ull;

    for (int ci = 0; ci < 32; ci++) {
        const float* ib = s_in + ci * 1224 + (4 * pbh) * 36 + 4 * pbw;
        const float* wp = s_w + ci * 144 + sub * 4;
        CONV_CI_BODY(ib, wp, 36, 16)
    }

    #pragma unroll
    for (int j = 0; j < 2; j++) {
        float v0[16], v1[16];
        #pragma unroll
        for (int q = 0; q < 16; q++) unpk(v0[q], v1[q], acc[j][q]);
        int co0 = cg * 16 + sub * 4 + j * 2;
        float bb0 = 4.f * b2[co0], bb1 = 4.f * b2[co0 + 1];
        #pragma unroll
        for (int i = 0; i < 2; i++)
            #pragma unroll
            for (int jj = 0; jj < 2; jj++) {
                float m0 = -1e30f, m1 = -1e30f;
                #pragma unroll
                for (int dy = 0; dy < 2; dy++)
                    #pragma unroll
                    for (int dx = 0; dx < 2; dx++) {
                        int q = (2 * i + dy) * 4 + (2 * jj + dx);
                        float t0 = fmaf(12.f, v0[q], bb0); t0 = LRELU(t0); m0 = fmaxf(m0, t0);
                        float t1 = fmaf(12.f, v1[q], bb1); t1 = LRELU(t1); m1 = fmaxf(m1, t1);
                    }
                int py = 2 * pbh + i, pxx = 2 * pbw + jj;
                g_H2[(b * 64 + co0) * 256 + py * 16 + pxx] = m0;
                g_H2[(b * 64 + co0 + 1) * 256 + py * 16 + pxx] = m1;
            }
    }
}

// ---------------------------------------------------------------------------
// Kernel 3: conv3 (64->128) + lrelu + pool + mean + dot(wc).  grid(32,4), 128.
// 128 threads = 16 pooled-blocks (4x4) x 8 cout-subgroups (4 couts each).
// s_in: 64ch x 18 x stride 20.  s_w: [ci][k][co0..31].
// ---------------------------------------------------------------------------
__global__ void __launch_bounds__(128, 1)
k3_conv(const float* __restrict__ w3,
        const float* __restrict__ b3,
        const float* __restrict__ wc,
        float* __restrict__ out) {
    extern __shared__ float sm[];
    float* s_in  = sm;                 // 64*18*20 = 23040
    float* s_w   = sm + 23040;         // 18432
    float* s_red = s_w + 18432;        // 32*65 = 2080

    const int b  = blockIdx.x;
    const int cg = blockIdx.y;
    const int tid = threadIdx.x;

    for (int i = tid * 4; i < 23040; i += 512)
        *(float4*)(s_in + i) = make_float4(0.f, 0.f, 0.f, 0.f);
    for (int i = tid; i < 18432; i += 128) {
        int co = i / 576; int r = i - co * 576;
        int ci = r / 9;   int k = r - ci * 9;
        s_w[(ci * 9 + k) * 32 + co] = w3[cg * 18432 + i];
    }
    __syncthreads();

    const float* hb = g_H2 + b * (64 * 256);
    for (int i = tid; i < 64 * 16 * 16; i += 128) {
        int c = i >> 8, r = (i >> 4) & 15, xx = i & 15;
        s_in[c * 360 + (r + 1) * 20 + (xx + 1)] = hb[i];
    }
    __syncthreads();

    const int px = tid & 15;
    const int sub = tid >> 4;          // 0..7 -> 4 couts each
    const int pbh = px >> 2, pbw = px & 3;

    ull acc[2][16];
    #pragma unroll
    for (int j = 0; j < 2; j++)
        #pragma unroll
        for (int q = 0; q < 16; q++) acc[j][q] = 0ull;

    for (int ci = 0; ci < 64; ci++) {
        const float* ib = s_in + ci * 360 + (4 * pbh) * 20 + 4 * pbw;
        const float* wp = s_w + ci * 288 + sub * 4;
        CONV_CI_BODY(ib, wp, 20, 32)
    }

    #pragma unroll
    for (int j = 0; j < 2; j++) {
        float v0[16], v1[16];
        #pragma unroll
        for (int q = 0; q < 16; q++) unpk(v0[q], v1[q], acc[j][q]);
        int lco0 = sub * 4 + j * 2;
        float bb0 = b3[cg * 32 + lco0], bb1 = b3[cg * 32 + lco0 + 1];
        #pragma unroll
        for (int i = 0; i < 2; i++)
            #pragma unroll
            for (int jj = 0; jj < 2; jj++) {
                float m0 = -1e30f, m1 = -1e30f;
                #pragma unroll
                for (int dy = 0; dy < 2; dy++)
                    #pragma unroll
                    for (int dx = 0; dx < 2; dx++) {
                        int q = (2 * i + dy) * 4 + (2 * jj + dx);
                        float t0 = v0[q] + bb0; t0 = LRELU(t0); m0 = fmaxf(m0, t0);
                        float t1 = v1[q] + bb1; t1 = LRELU(t1); m1 = fmaxf(m1, t1);
                    }
                int ppx = (2 * pbh + i) * 8 + (2 * pbw + jj);
                s_red[lco0 * 65 + ppx] = m0;
                s_red[(lco0 + 1) * 65 + ppx] = m1;
            }
    }
    __syncthreads();

    if (tid < 32) {
        float s = 0.f;
        #pragma unroll 8
        for (int p2 = 0; p2 < 64; p2++) s += s_red[tid * 65 + p2];
        float part = wc[cg * 32 + tid] * s * (1.0f / 64.0f);
        #pragma unroll
        for (int off = 16; off; off >>= 1)
            part += __shfl_down_sync(0xffffffffu, part, off);
        if (tid == 0) atomicAdd(&out[b], part);
    }
}

// out[b] = bc before k3's atomic accumulation.
__global__ void k_init(float* __restrict__ out, const float* __restrict__ bc) {
    if (threadIdx.x < 32) out[threadIdx.x] = bc[0];
}

extern "C" void kernel_launch(void* const* d_in, const int* in_sizes, int n_in,
                              void* d_out, int out_size) {
    const float* x  = (const float*)d_in[0];
    const float* w1 = (const float*)d_in[1];
    const float* b1 = (const float*)d_in[2];
    const float* w2 = (const float*)d_in[3];
    const float* b2 = (const float*)d_in[4];
    const float* w3 = (const float*)d_in[5];
    const float* b3 = (const float*)d_in[6];
    const float* wc = (const float*)d_in[7];
    const float* bc = (const float*)d_in[8];
    float* out = (float*)d_out;

    const size_t sm1 = (17952 + 144) * sizeof(float);          //  72 KB
    const size_t sm2 = (39168 + 4608) * sizeof(float);         // 175 KB
    const size_t sm3 = (23040 + 18432 + 2080) * sizeof(float); // 174 KB

    cudaFuncSetAttribute(k1_conv, cudaFuncAttributeMaxDynamicSharedMemorySize, (int)sm1);
    cudaFuncSetAttribute(k2_conv, cudaFuncAttributeMaxDynamicSharedMemorySize, (int)sm2);
    cudaFuncSetAttribute(k3_conv, cudaFuncAttributeMaxDynamicSharedMemorySize, (int)sm3);

    k1_conv<<<dim3(32, 8), 256, sm1>>>(x, w1, b1);
    k2_conv<<<dim3(32, 4), 256, sm2>>>(w2, b2);
    k_init<<<1, 32>>>(out, bc);
    k3_conv<<<dim3(32, 4), 128, sm3>>>(w3, b3, wc, out);
}

// round 8
// speedup vs baseline: 1.3559x; 1.1665x over previous
#include <cuda_runtime.h>

// ---------------------------------------------------------------------------
// GCN_84559316124289 — collapsed graph + f32x2 FMA, latency-tuned.
//   P1 = pool(lrelu(conv1(x)+b1))
//   H2 = pool(lrelu(12*conv2w(P1) + 4*b2))
//   H3 = pool(lrelu(conv3(H2)+b3));  out[b] = wc . mean(H3) + bc
//
// Per thread: 4 couts (2 f32x2 pairs) x 8 conv px (2x4 -> 1x2 pooled).
// Warps organized so all 32 lanes share one cout-subgroup -> weight LDS.128
// is a broadcast. Weight smem uses padded strides (8/20/36) so the staging
// stores are conflict-free and loop loads stay 16B-aligned.
// ---------------------------------------------------------------------------

typedef unsigned long long ull;

__device__ __forceinline__ ull dup2(float x) {
    ull r; asm("mov.b64 %0, {%1, %1};" : "=l"(r) : "f"(x)); return r;
}
__device__ __forceinline__ void ffma2(ull& d, ull a, ull b) {
    asm("fma.rn.f32x2 %0, %1, %2, %0;" : "+l"(d) : "l"(a), "l"(b));
}
__device__ __forceinline__ void unpk(float& lo, float& hi, ull v) {
    asm("mov.b64 {%0, %1}, %2;" : "=f"(lo), "=f"(hi) : "l"(v));
}

#define LRELU(t) ((t) > 0.f ? (t) : 0.2f * (t))

__device__ float g_P1[32 * 32 * 32 * 32];   // [B, 32, 32, 32]
__device__ float g_H2[32 * 64 * 16 * 16];   // [B, 64, 16, 16]

// 1x2-pooled-tile micro kernel: 4x6 patch (dup'd), 9 broadcast weight LDS.128,
// 16 FFMA2 per k. RS = s_in row stride, WS = s_w k-stride (floats).
#define CONV_CI_12(IB, WP, RS, WS)                                             \
    {                                                                          \
        ull pd[4][6];                                                          \
        _Pragma("unroll")                                                      \
        for (int r = 0; r < 4; r++) {                                          \
            float4 a4 = *(const float4*)((IB) + r * (RS));                     \
            float2 b2v = *(const float2*)((IB) + r * (RS) + 4);                \
            pd[r][0] = dup2(a4.x);  pd[r][1] = dup2(a4.y);                     \
            pd[r][2] = dup2(a4.z);  pd[r][3] = dup2(a4.w);                     \
            pd[r][4] = dup2(b2v.x); pd[r][5] = dup2(b2v.y);                    \
        }                                                                      \
        _Pragma("unroll")                                                      \
        for (int k = 0; k < 9; k++) {                                          \
            ulonglong2 w = *(const ulonglong2*)((WP) + k * (WS));              \
            int ky = k / 3, kx = k - ky * 3;                                   \
            _Pragma("unroll")                                                  \
            for (int dy = 0; dy < 2; dy++)                                     \
                _Pragma("unroll")                                              \
                for (int dx = 0; dx < 4; dx++) {                               \
                    ull pv = pd[dy + ky][dx + kx];                             \
                    int q = dy * 4 + dx;                                       \
                    ffma2(acc[0][q], pv, w.x);                                 \
                    ffma2(acc[1][q], pv, w.y);                                 \
                }                                                              \
        }                                                                      \
    }

// ---------------------------------------------------------------------------
// Kernel 1: conv1 (4->32) + lrelu + pool.  grid(32,8) block 512.
// 512 threads = 512 1x2-pooled tiles (32x16 groups), all on cg's 4 couts.
// s_in: 4ch x 66 x stride 68.  s_w: [ci*9+k]*8 + co.
// ---------------------------------------------------------------------------
__global__ void __launch_bounds__(512, 1)
k1_conv(const float* __restrict__ x,
        const float* __restrict__ w1,
        const float* __restrict__ b1,
        const float* __restrict__ bc,
        float* __restrict__ out) {
    extern __shared__ float sm[];
    float* s_in = sm;                  // 4*4488 = 17952
    float* s_w  = sm + 17952;          // 36*8 = 288

    const int b  = blockIdx.x;
    const int cg = blockIdx.y;
    const int tid = threadIdx.x;

    if (cg == 0 && tid == 0) out[b] = bc[0];

    const float* xb = x + b * 16384;
    for (int j = tid; j < 4096; j += 512) {
        float4 v = *(const float4*)(xb + j * 4);
        int c = j >> 10, r = (j >> 4) & 63, x0 = (j & 15) * 4;
        float* d = s_in + c * 4488 + (r + 1) * 68 + x0 + 1;
        d[0] = v.x; d[1] = v.y; d[2] = v.z; d[3] = v.w;
    }
    // halo per ch: rows {0,65} full (136) + rows 1..64 cols {0,65} (128)
    for (int i = tid; i < 4 * 264; i += 512) {
        int c = i / 264, t = i - c * 264;
        int row, col;
        if (t < 136) { row = (t >= 68) ? 65 : 0; col = t % 68; }
        else { int tt = t - 136; row = 1 + (tt >> 1); col = (tt & 1) ? 65 : 0; }
        s_in[c * 4488 + row * 68 + col] = 0.f;
    }
    if (tid < 144) {
        int co = tid / 36, r = tid - co * 36;
        s_w[r * 8 + co] = w1[cg * 144 + tid];
    }
    __syncthreads();

    const int gh = tid >> 4, gw = tid & 15;   // pooled row, pooled col-pair

    ull acc[2][8];
    #pragma unroll
    for (int j = 0; j < 2; j++)
        #pragma unroll
        for (int q = 0; q < 8; q++) acc[j][q] = 0ull;

    #pragma unroll
    for (int ci = 0; ci < 4; ci++) {
        const float* ib = s_in + ci * 4488 + (2 * gh) * 68 + 4 * gw;
        const float* wp = s_w + ci * 72;
        CONV_CI_12(ib, wp, 68, 8)
    }

    #pragma unroll
    for (int j = 0; j < 2; j++) {
        float v0[8], v1[8];
        #pragma unroll
        for (int q = 0; q < 8; q++) unpk(v0[q], v1[q], acc[j][q]);
        int co0 = cg * 4 + 2 * j;
        float bb0 = b1[co0], bb1 = b1[co0 + 1];
        #pragma unroll
        for (int c2 = 0; c2 < 2; c2++) {
            float m0 = -1e30f, m1 = -1e30f;
            #pragma unroll
            for (int dy = 0; dy < 2; dy++)
                #pragma unroll
                for (int dx = 0; dx < 2; dx++) {
                    int q = dy * 4 + 2 * c2 + dx;
                    float t0 = v0[q] + bb0; t0 = LRELU(t0); m0 = fmaxf(m0, t0);
                    float t1 = v1[q] + bb1; t1 = LRELU(t1); m1 = fmaxf(m1, t1);
                }
            g_P1[(b * 32 + co0) * 1024 + gh * 32 + 2 * gw + c2] = m0;
            g_P1[(b * 32 + co0 + 1) * 1024 + gh * 32 + 2 * gw + c2] = m1;
        }
    }
}

// ---------------------------------------------------------------------------
// Kernel 2: 12*conv2w (32->64) + 4*b2, lrelu, pool.  grid(32,4) block 512.
// 4 subs (4 couts) x 128 tiles; sub = tid>>7 so each warp = one sub.
// s_in: 32ch x 34 x stride 36.  s_w: [ci*9+k]*20 + co(0..15).
// ---------------------------------------------------------------------------
__global__ void __launch_bounds__(512, 1)
k2_conv(const float* __restrict__ w2,
        const float* __restrict__ b2) {
    extern __shared__ float sm[];
    float* s_in = sm;                  // 32*1224 = 39168
    float* s_w  = sm + 39168;          // 288*20 = 5760

    const int b  = blockIdx.x;
    const int cg = blockIdx.y;
    const int tid = threadIdx.x;

    const float* pb = g_P1 + b * 32768;
    for (int j = tid; j < 8192; j += 512) {
        float4 v = *(const float4*)(pb + j * 4);
        int c = j >> 8, r = (j >> 3) & 31, x0 = (j & 7) * 4;
        float* d = s_in + c * 1224 + (r + 1) * 36 + x0 + 1;
        d[0] = v.x; d[1] = v.y; d[2] = v.z; d[3] = v.w;
    }
    for (int i = tid; i < 32 * 136; i += 512) {
        int c = i / 136, t = i - c * 136;
        int row, col;
        if (t < 72) { row = (t >= 36) ? 33 : 0; col = t % 36; }
        else { int tt = t - 72; row = 1 + (tt >> 1); col = (tt & 1) ? 33 : 0; }
        s_in[c * 1224 + row * 36 + col] = 0.f;
    }
    for (int i = tid * 4; i < 4608; i += 2048) {
        float4 wv = *(const float4*)(w2 + cg * 4608 + i);
        int co = i / 288, r = i - co * 288;
        s_w[(r + 0) * 20 + co] = wv.x;
        s_w[(r + 1) * 20 + co] = wv.y;
        s_w[(r + 2) * 20 + co] = wv.z;
        s_w[(r + 3) * 20 + co] = wv.w;
    }
    __syncthreads();

    const int sub = tid >> 7;          // 0..3 -> couts sub*4..+3
    const int pxg = tid & 127;
    const int gh = pxg >> 3, gw = pxg & 7;

    ull acc[2][8];
    #pragma unroll
    for (int j = 0; j < 2; j++)
        #pragma unroll
        for (int q = 0; q < 8; q++) acc[j][q] = 0ull;

    for (int ci = 0; ci < 32; ci++) {
        const float* ib = s_in + ci * 1224 + (2 * gh) * 36 + 4 * gw;
        const float* wp = s_w + ci * 180 + sub * 4;
        CONV_CI_12(ib, wp, 36, 20)
    }

    #pragma unroll
    for (int j = 0; j < 2; j++) {
        float v0[8], v1[8];
        #pragma unroll
        for (int q = 0; q < 8; q++) unpk(v0[q], v1[q], acc[j][q]);
        int co0 = cg * 16 + sub * 4 + 2 * j;
        float bb0 = 4.f * b2[co0], bb1 = 4.f * b2[co0 + 1];
        #pragma unroll
        for (int c2 = 0; c2 < 2; c2++) {
            float m0 = -1e30f, m1 = -1e30f;
            #pragma unroll
            for (int dy = 0; dy < 2; dy++)
                #pragma unroll
                for (int dx = 0; dx < 2; dx++) {
                    int q = dy * 4 + 2 * c2 + dx;
                    float t0 = fmaf(12.f, v0[q], bb0); t0 = LRELU(t0); m0 = fmaxf(m0, t0);
                    float t1 = fmaf(12.f, v1[q], bb1); t1 = LRELU(t1); m1 = fmaxf(m1, t1);
                }
            g_H2[(b * 64 + co0) * 256 + gh * 16 + 2 * gw + c2] = m0;
            g_H2[(b * 64 + co0 + 1) * 256 + gh * 16 + 2 * gw + c2] = m1;
        }
    }
}

// ---------------------------------------------------------------------------
// Kernel 3: conv3 (64->128) + lrelu + pool + mean + dot(wc).  grid(32,4), 256.
// 8 subs (4 couts) x 32 tiles; sub = tid>>5 so each warp = one sub.
// s_in: 64ch x 18 x stride 20.  s_w: [ci*9+k]*36 + co(0..31).
// ---------------------------------------------------------------------------
__global__ void __launch_bounds__(256, 1)
k3_conv(const float* __restrict__ w3,
        const float* __restrict__ b3,
        const float* __restrict__ wc,
        float* __restrict__ out) {
    extern __shared__ float sm[];
    float* s_in  = sm;                 // 64*360 = 23040
    float* s_w   = sm + 23040;         // 576*36 = 20736
    float* s_red = s_w + 20736;        // 32*65 = 2080

    const int b  = blockIdx.x;
    const int cg = blockIdx.y;
    const int tid = threadIdx.x;

    const float* hb = g_H2 + b * 16384;
    for (int j = tid; j < 4096; j += 256) {
        float4 v = *(const float4*)(hb + j * 4);
        int c = j >> 6, r = (j >> 2) & 15, x0 = (j & 3) * 4;
        float* d = s_in + c * 360 + (r + 1) * 20 + x0 + 1;
        d[0] = v.x; d[1] = v.y; d[2] = v.z; d[3] = v.w;
    }
    for (int i = tid; i < 64 * 72; i += 256) {
        int c = i / 72, t = i - c * 72;
        int row, col;
        if (t < 40) { row = (t >= 20) ? 17 : 0; col = t % 20; }
        else { int tt = t - 40; row = 1 + (tt >> 1); col = (tt & 1) ? 17 : 0; }
        s_in[c * 360 + row * 20 + col] = 0.f;
    }
    for (int i = tid * 4; i < 18432; i += 1024) {
        float4 wv = *(const float4*)(w3 + cg * 18432 + i);
        int co = i / 576, r = i - co * 576;
        s_w[(r + 0) * 36 + co] = wv.x;
        s_w[(r + 1) * 36 + co] = wv.y;
        s_w[(r + 2) * 36 + co] = wv.z;
        s_w[(r + 3) * 36 + co] = wv.w;
    }
    __syncthreads();

    const int sub = tid >> 5;          // 0..7 -> couts sub*4..+3
    const int pxg = tid & 31;
    const int gh = pxg >> 2, gw = pxg & 3;

    ull acc[2][8];
    #pragma unroll
    for (int j = 0; j < 2; j++)
        #pragma unroll
        for (int q = 0; q < 8; q++) acc[j][q] = 0ull;

    for (int ci = 0; ci < 64; ci++) {
        const float* ib = s_in + ci * 360 + (2 * gh) * 20 + 4 * gw;
        const float* wp = s_w + ci * 324 + sub * 4;
        CONV_CI_12(ib, wp, 20, 36)
    }

    #pragma unroll
    for (int j = 0; j < 2; j++) {
        float v0[8], v1[8];
        #pragma unroll
        for (int q = 0; q < 8; q++) unpk(v0[q], v1[q], acc[j][q]);
        int lco0 = sub * 4 + 2 * j;
        float bb0 = b3[cg * 32 + lco0], bb1 = b3[cg * 32 + lco0 + 1];
        #pragma unroll
        for (int c2 = 0; c2 < 2; c2++) {
            float m0 = -1e30f, m1 = -1e30f;
            #pragma unroll
            for (int dy = 0; dy < 2; dy++)
                #pragma unroll
                for (int dx = 0; dx < 2; dx++) {
                    int q = dy * 4 + 2 * c2 + dx;
                    float t0 = v0[q] + bb0; t0 = LRELU(t0); m0 = fmaxf(m0, t0);
                    float t1 = v1[q] + bb1; t1 = LRELU(t1); m1 = fmaxf(m1, t1);
                }
            int ppx = gh * 8 + 2 * gw + c2;
            s_red[lco0 * 65 + ppx] = m0;
            s_red[(lco0 + 1) * 65 + ppx] = m1;
        }
    }
    __syncthreads();

    if (tid < 32) {
        float s = 0.f;
        #pragma unroll 8
        for (int p2 = 0; p2 < 64; p2++) s += s_red[tid * 65 + p2];
        float part = wc[cg * 32 + tid] * s * (1.0f / 64.0f);
        #pragma unroll
        for (int off = 16; off; off >>= 1)
            part += __shfl_down_sync(0xffffffffu, part, off);
        if (tid == 0) atomicAdd(&out[b], part);
    }
}

extern "C" void kernel_launch(void* const* d_in, const int* in_sizes, int n_in,
                              void* d_out, int out_size) {
    const float* x  = (const float*)d_in[0];
    const float* w1 = (const float*)d_in[1];
    const float* b1 = (const float*)d_in[2];
    const float* w2 = (const float*)d_in[3];
    const float* b2 = (const float*)d_in[4];
    const float* w3 = (const float*)d_in[5];
    const float* b3 = (const float*)d_in[6];
    const float* wc = (const float*)d_in[7];
    const float* bc = (const float*)d_in[8];
    float* out = (float*)d_out;

    const size_t sm1 = (17952 + 288) * sizeof(float);           //  73 KB
    const size_t sm2 = (39168 + 5760) * sizeof(float);          // 180 KB
    const size_t sm3 = (23040 + 20736 + 2080) * sizeof(float);  // 183 KB

    cudaFuncSetAttribute(k1_conv, cudaFuncAttributeMaxDynamicSharedMemorySize, (int)sm1);
    cudaFuncSetAttribute(k2_conv, cudaFuncAttributeMaxDynamicSharedMemorySize, (int)sm2);
    cudaFuncSetAttribute(k3_conv, cudaFuncAttributeMaxDynamicSharedMemorySize, (int)sm3);

    k1_conv<<<dim3(32, 8), 512, sm1>>>(x, w1, b1, bc, out);
    k2_conv<<<dim3(32, 4), 512, sm2>>>(w2, b2);
    k3_conv<<<dim3(32, 4), 256, sm3>>>(w3, b3, wc, out);
}